// round 15
// baseline (speedup 1.0000x reference)
#include <cuda_runtime.h>

#define N_NODES 50000
#define N_EDGES 800000
#define FEATS 128
#define HID 64

// ---------------- scratch (device globals; no allocation allowed) ----------
__device__ float g_x1[N_NODES * HID];
__device__ float g_x2[N_NODES * HID];
__device__ float g_h[N_NODES * HID];
__device__ float g_inv[N_NODES];
__device__ int   g_cnt[N_NODES];
__device__ int   g_fill[N_NODES];
__device__ int   g_rowptr[N_NODES + 1];
__device__ int   g_bsum[256];
__device__ int   g_boff[256];
__device__ int   g_esrc[N_EDGES];
__device__ float g_ecoef[N_EDGES];

// packed bf16x2 B-fragment tables (m16n8k16 layout)
// L1: 8 slots | per block-set: 16 slots (W 0-7, Aa 8-11, Ab 12-15)
// slot = 512 u32 (8 ntiles x 32 lanes x 2 regs)
#define PACK_L1 0
#define PACK_B2 4096
#define PACK_B3 (4096 + 8192)
#define PACK_B4 (4096 + 2 * 8192)
#define PACK_TOT (4096 + 3 * 8192)
__device__ unsigned g_pH[PACK_TOT];
__device__ unsigned g_pL[PACK_TOT];

__device__ __forceinline__ unsigned bfpack(float hv, float lv) {
    unsigned r;
    asm("cvt.rn.bf16x2.f32 %0, %1, %2;" : "=r"(r) : "f"(hv), "f"(lv));
    return r;
}
__device__ __forceinline__ float bflo(unsigned p) { return __uint_as_float(p << 16); }
__device__ __forceinline__ float bfhi(unsigned p) { return __uint_as_float(p & 0xffff0000u); }

__device__ __forceinline__ void bfsplit(float lv, float hv, unsigned& ph, unsigned& pl) {
    ph = bfpack(hv, lv);
    pl = bfpack(hv - bfhi(ph), lv - bflo(ph));
}

__device__ __forceinline__ void mma16(float* d, unsigned a0, unsigned a1,
                                      unsigned a2, unsigned a3,
                                      unsigned b0, unsigned b1) {
    asm volatile(
        "mma.sync.aligned.m16n8k16.row.col.f32.bf16.bf16.f32 "
        "{%0,%1,%2,%3}, {%4,%5,%6,%7}, {%8,%9}, {%0,%1,%2,%3};"
        : "+f"(d[0]), "+f"(d[1]), "+f"(d[2]), "+f"(d[3])
        : "r"(a0), "r"(a1), "r"(a2), "r"(a3), "r"(b0), "r"(b1));
}

__device__ __forceinline__ void mma3(float* d,
                                     unsigned ah0, unsigned ah1, unsigned ah2, unsigned ah3,
                                     unsigned al0, unsigned al1, unsigned al2, unsigned al3,
                                     unsigned bh0, unsigned bh1, unsigned bl0, unsigned bl1) {
    mma16(d, al0, al1, al2, al3, bh0, bh1);
    mma16(d, ah0, ah1, ah2, ah3, bl0, bl1);
    mma16(d, ah0, ah1, ah2, ah3, bh0, bh1);
}

// ---------------- graph prep ------------------------------------------------
__global__ void k_zero_int(int* a, int* b, int n) {
    int i = blockIdx.x * blockDim.x + threadIdx.x;
    if (i < n) { a[i] = 0; b[i] = 0; }
}

__global__ void k_deg(const int* __restrict__ edges) {
    int e = blockIdx.x * blockDim.x + threadIdx.x;
    if (e < N_EDGES) atomicAdd(&g_cnt[edges[N_EDGES + e]], 1);
}

#define SCAN_B ((N_NODES + 255) / 256)   // 196

__global__ void k_scan1() {
    __shared__ int sm[256];
    int b = blockIdx.x, t = threadIdx.x;
    int i = b * 256 + t;
    int v = (i < N_NODES) ? g_cnt[i] : 0;
    if (i < N_NODES) g_inv[i] = rsqrtf(fmaxf((float)v, 1.0f));
    sm[t] = v;
    __syncthreads();
    for (int off = 1; off < 256; off <<= 1) {
        int u = (t >= off) ? sm[t - off] : 0;
        __syncthreads();
        sm[t] += u;
        __syncthreads();
    }
    if (i < N_NODES) g_rowptr[i] = sm[t] - v;
    if (t == 255) g_bsum[b] = sm[255];
}

__global__ void k_scan2() {
    __shared__ int sm[256];
    int t = threadIdx.x;
    int v = (t < SCAN_B) ? g_bsum[t] : 0;
    sm[t] = v;
    __syncthreads();
    for (int off = 1; off < 256; off <<= 1) {
        int u = (t >= off) ? sm[t - off] : 0;
        __syncthreads();
        sm[t] += u;
        __syncthreads();
    }
    if (t < SCAN_B) g_boff[t] = sm[t] - v;
    if (t == 255) g_rowptr[N_NODES] = sm[255];
}

__global__ void k_scan3() {
    int i = blockIdx.x * 256 + threadIdx.x;
    if (i < N_NODES) g_rowptr[i] += g_boff[blockIdx.x];
}

__global__ void k_fill(const int* __restrict__ edges) {
    int e = blockIdx.x * blockDim.x + threadIdx.x;
    if (e < N_EDGES) {
        int s = edges[e];
        int d = edges[N_EDGES + e];
        int pos = g_rowptr[d] + atomicAdd(&g_fill[d], 1);
        g_esrc[pos] = s;
        g_ecoef[pos] = g_inv[s] * g_inv[d];
    }
}

// pack all layer weights into m16n8k16 B-fragment order, bf16 hi/lo split
__global__ void k_pack(
    const float* __restrict__ W1,
    const float* __restrict__ W2, const float* __restrict__ A2a, const float* __restrict__ A2b,
    const float* __restrict__ W3, const float* __restrict__ A3a, const float* __restrict__ A3b,
    const float* __restrict__ W4, const float* __restrict__ A4a, const float* __restrict__ A4b)
{
    int t = blockIdx.x * blockDim.x + threadIdx.x;
    if (t >= PACK_TOT) return;

    int s, rem;
    const float *W = 0, *Aa = 0, *Ab = 0;
    bool isL1 = (t < PACK_B2);
    if (isL1) {
        s = t >> 9; rem = t & 511; W = W1;
    } else {
        int r = (t - PACK_B2) >> 13;
        int within = (t - PACK_B2) & 8191;
        s = within >> 9; rem = within & 511;
        if (r == 0)      { W = W2; Aa = A2a; Ab = A2b; }
        else if (r == 1) { W = W3; Aa = A3a; Ab = A3b; }
        else             { W = W4; Aa = A4a; Ab = A4b; }
    }
    int nt = rem >> 6;
    int lane = (rem >> 1) & 31;
    int j = rem & 1;
    int tig = lane & 3, gid = lane >> 2;
    int n = nt * 8 + gid;
    int kk = 2 * tig + j * 8;

    float v0, v1;
    if (isL1 || s < 8) {
        int k = s * 16 + kk;
        v0 = W[n * 128 + k]; v1 = W[n * 128 + k + 1];
    } else if (s < 12) {
        int k = (s - 8) * 16 + kk;
        v0 = Aa[n * 64 + k]; v1 = Aa[n * 64 + k + 1];
    } else {
        int k = (s - 12) * 16 + kk;
        v0 = Ab[n * 64 + k]; v1 = Ab[n * 64 + k + 1];
    }
    unsigned ph, pl;
    bfsplit(v0, v1, ph, pl);
    g_pH[t] = ph;
    g_pL[t] = pl;
}

// ---------------- CSR pull aggregation: h[n] = sum_e coef*x[src] -----------
// 16 threads per node, thread q handles feats [4q, 4q+4)
__global__ __launch_bounds__(256) void k_csr(const float* __restrict__ x) {
    int idx = blockIdx.x * blockDim.x + threadIdx.x;
    int n = idx >> 4;
    if (n >= N_NODES) return;
    int q4 = (idx & 15) * 4;
    int beg = g_rowptr[n];
    int end = g_rowptr[n + 1];
    float4 acc = make_float4(0.f, 0.f, 0.f, 0.f);
    int e = beg;
    for (; e + 4 <= end; e += 4) {
        int s0 = g_esrc[e],     s1 = g_esrc[e + 1];
        int s2 = g_esrc[e + 2], s3 = g_esrc[e + 3];
        float c0 = g_ecoef[e],     c1 = g_ecoef[e + 1];
        float c2 = g_ecoef[e + 2], c3 = g_ecoef[e + 3];
        float4 v0 = *(const float4*)&x[s0 * HID + q4];
        float4 v1 = *(const float4*)&x[s1 * HID + q4];
        float4 v2 = *(const float4*)&x[s2 * HID + q4];
        float4 v3 = *(const float4*)&x[s3 * HID + q4];
        acc.x += v0.x * c0 + v1.x * c1 + v2.x * c2 + v3.x * c3;
        acc.y += v0.y * c0 + v1.y * c1 + v2.y * c2 + v3.y * c3;
        acc.z += v0.z * c0 + v1.z * c1 + v2.z * c2 + v3.z * c3;
        acc.w += v0.w * c0 + v1.w * c1 + v2.w * c2 + v3.w * c3;
    }
    for (; e < end; e++) {
        int s = g_esrc[e];
        float c = g_ecoef[e];
        float4 v = *(const float4*)&x[s * HID + q4];
        acc.x += v.x * c;
        acc.y += v.y * c;
        acc.z += v.z * c;
        acc.w += v.w * c;
    }
    *(float4*)&g_h[n * HID + q4] = acc;
}

// ---------------- layer 1: relu(x0 @ W1^T + b1), smem-free bf16x3 ----------
// launch_bounds(256,4): cap regs at 64 -> 4 CTAs/SM (was 3 @ 68 regs)
__global__ __launch_bounds__(256, 4) void k_layer1(
    const float* __restrict__ x0, const float* __restrict__ b1,
    float* __restrict__ out)
{
    int tid = threadIdx.x;
    int lane = tid & 31, wid = tid >> 5;
    int tig = lane & 3, gid = lane >> 2;
    int nodeA = blockIdx.x * 128 + wid * 16 + gid;
    int nodeB = nodeA + 8;
    bool vA = nodeA < N_NODES, vB = nodeB < N_NODES;
    const float* xA = x0 + (long long)nodeA * FEATS;
    const float* xB = x0 + (long long)nodeB * FEATS;

    const unsigned* gH = g_pH + PACK_L1 + lane * 2;
    const unsigned* gL = g_pL + PACK_L1 + lane * 2;

    float acc[8][4] = {};
    const float2 z2 = make_float2(0.f, 0.f);

#pragma unroll 2
    for (int ks = 0; ks < 8; ks++) {
        int c = ks * 16 + 2 * tig;
        float2 fA0 = vA ? *(const float2*)&xA[c] : z2;
        float2 fA2 = vA ? *(const float2*)&xA[c + 8] : z2;
        float2 fB0 = vB ? *(const float2*)&xB[c] : z2;
        float2 fB2 = vB ? *(const float2*)&xB[c + 8] : z2;
        unsigned ah0, al0, ah1, al1, ah2, al2, ah3, al3;
        bfsplit(fA0.x, fA0.y, ah0, al0);
        bfsplit(fB0.x, fB0.y, ah1, al1);
        bfsplit(fA2.x, fA2.y, ah2, al2);
        bfsplit(fB2.x, fB2.y, ah3, al3);
        const unsigned* pH_ = gH + ks * 512;
        const unsigned* pL_ = gL + ks * 512;
#pragma unroll
        for (int nt = 0; nt < 8; nt++) {
            uint2 wh = *(const uint2*)(pH_ + nt * 64);
            uint2 wl = *(const uint2*)(pL_ + nt * 64);
            mma3(acc[nt], ah0, ah1, ah2, ah3, al0, al1, al2, al3, wh.x, wh.y, wl.x, wl.y);
        }
    }

#pragma unroll
    for (int nt = 0; nt < 8; nt++) {
        int col = nt * 8 + 2 * tig;
        float2 bb = *(const float2*)&b1[col];
        if (vA) {
            float2 o;
            o.x = fmaxf(acc[nt][0] + bb.x, 0.f);
            o.y = fmaxf(acc[nt][1] + bb.y, 0.f);
            *(float2*)&out[nodeA * HID + col] = o;
        }
        if (vB) {
            float2 o;
            o.x = fmaxf(acc[nt][2] + bb.x, 0.f);
            o.y = fmaxf(acc[nt][3] + bb.y, 0.f);
            *(float2*)&out[nodeB * HID + col] = o;
        }
    }
}

// ---------------- block: relu(cat[x,h]@W^T + (x@Aa^T)*(x@Ab^T)) ------------
// x/h staged in smem (coalesced, reused); B fragments (bf16) from L1.
// launch_bounds(256,3): cap regs at 85 -> 3 CTAs/SM (smem 3*68KB=204KB fits)
#define XS_STRIDE 68
#define BLK_SMEM (128 * XS_STRIDE * 2 * 4)   // 69632 bytes

__global__ __launch_bounds__(256, 3) void k_block(
    const float* __restrict__ x, const unsigned* __restrict__ pH,
    const unsigned* __restrict__ pL, float* __restrict__ out)
{
    extern __shared__ float sm[];
    float* xs = sm;                    // [128][68]
    float* hs = sm + 128 * XS_STRIDE;  // [128][68]

    int tid = threadIdx.x;
    int n0 = blockIdx.x * 128;

    for (int idx = tid; idx < 128 * 16; idx += 256) {
        int r = idx >> 4;
        int c4 = (idx & 15) * 4;
        int node = n0 + r;
        float4 xv, hv;
        if (node < N_NODES) {
            xv = *(const float4*)&x[node * HID + c4];
            hv = *(const float4*)&g_h[node * HID + c4];
        } else {
            xv = make_float4(0.f, 0.f, 0.f, 0.f);
            hv = xv;
        }
        *(float4*)&xs[r * XS_STRIDE + c4] = xv;
        *(float4*)&hs[r * XS_STRIDE + c4] = hv;
    }
    __syncthreads();

    int lane = tid & 31, wid = tid >> 5;
    int tig = lane & 3, gid = lane >> 2;
    int row0 = wid * 16 + gid;
    int nodeA = n0 + row0;
    int nodeB = nodeA + 8;
    bool vA = nodeA < N_NODES, vB = nodeB < N_NODES;

    const unsigned* gH = pH + lane * 2;
    const unsigned* gL = pL + lane * 2;

#pragma unroll 1
    for (int half = 0; half < 2; half++) {
        int ntoff = half * 4 * 64;
        float accW[4][4] = {}, accA[4][4] = {}, accB[4][4] = {};

        // phase X: A = x; W slots 0-3, Aa slots 8-11, Ab slots 12-15
        for (int ks = 0; ks < 4; ks++) {
            const float* xr = &xs[row0 * XS_STRIDE + ks * 16 + 2 * tig];
            float2 f0 = *(const float2*)xr;
            float2 f2 = *(const float2*)(xr + 8);
            float2 f1 = *(const float2*)(xr + 8 * XS_STRIDE);
            float2 f3 = *(const float2*)(xr + 8 * XS_STRIDE + 8);
            unsigned ah0, al0, ah1, al1, ah2, al2, ah3, al3;
            bfsplit(f0.x, f0.y, ah0, al0);
            bfsplit(f1.x, f1.y, ah1, al1);
            bfsplit(f2.x, f2.y, ah2, al2);
            bfsplit(f3.x, f3.y, ah3, al3);
#pragma unroll
            for (int nt = 0; nt < 4; nt++) {
                uint2 wh = *(const uint2*)(gH + ks * 512 + ntoff + nt * 64);
                uint2 wl = *(const uint2*)(gL + ks * 512 + ntoff + nt * 64);
                mma3(accW[nt], ah0, ah1, ah2, ah3, al0, al1, al2, al3, wh.x, wh.y, wl.x, wl.y);
                uint2 gh = *(const uint2*)(gH + (8 + ks) * 512 + ntoff + nt * 64);
                uint2 gl = *(const uint2*)(gL + (8 + ks) * 512 + ntoff + nt * 64);
                mma3(accA[nt], ah0, ah1, ah2, ah3, al0, al1, al2, al3, gh.x, gh.y, gl.x, gl.y);
                uint2 kh = *(const uint2*)(gH + (12 + ks) * 512 + ntoff + nt * 64);
                uint2 kl = *(const uint2*)(gL + (12 + ks) * 512 + ntoff + nt * 64);
                mma3(accB[nt], ah0, ah1, ah2, ah3, al0, al1, al2, al3, kh.x, kh.y, kl.x, kl.y);
            }
        }

        // phase H: A = h; W slots 4-7
        for (int ks = 0; ks < 4; ks++) {
            const float* hr = &hs[row0 * XS_STRIDE + ks * 16 + 2 * tig];
            float2 f0 = *(const float2*)hr;
            float2 f2 = *(const float2*)(hr + 8);
            float2 f1 = *(const float2*)(hr + 8 * XS_STRIDE);
            float2 f3 = *(const float2*)(hr + 8 * XS_STRIDE + 8);
            unsigned ah0, al0, ah1, al1, ah2, al2, ah3, al3;
            bfsplit(f0.x, f0.y, ah0, al0);
            bfsplit(f1.x, f1.y, ah1, al1);
            bfsplit(f2.x, f2.y, ah2, al2);
            bfsplit(f3.x, f3.y, ah3, al3);
#pragma unroll
            for (int nt = 0; nt < 4; nt++) {
                uint2 wh = *(const uint2*)(gH + (4 + ks) * 512 + ntoff + nt * 64);
                uint2 wl = *(const uint2*)(gL + (4 + ks) * 512 + ntoff + nt * 64);
                mma3(accW[nt], ah0, ah1, ah2, ah3, al0, al1, al2, al3, wh.x, wh.y, wl.x, wl.y);
            }
        }

#pragma unroll
        for (int nt = 0; nt < 4; nt++) {
            int col = half * 32 + nt * 8 + 2 * tig;
            if (vA) {
                float2 o;
                o.x = fmaxf(accW[nt][0] + accA[nt][0] * accB[nt][0], 0.f);
                o.y = fmaxf(accW[nt][1] + accA[nt][1] * accB[nt][1], 0.f);
                *(float2*)&out[nodeA * HID + col] = o;
            }
            if (vB) {
                float2 o;
                o.x = fmaxf(accW[nt][2] + accA[nt][2] * accB[nt][2], 0.f);
                o.y = fmaxf(accW[nt][3] + accA[nt][3] * accB[nt][3], 0.f);
                *(float2*)&out[nodeB * HID + col] = o;
            }
        }
    }
}

// ---------------- launch ----------------------------------------------------
extern "C" void kernel_launch(void* const* d_in, const int* in_sizes, int n_in,
                              void* d_out, int out_size)
{
    const float* x0 = (const float*)d_in[0];
    const int* edg  = (const int*)d_in[1];   // int32: [2][N_EDGES]
    const float* W1  = (const float*)d_in[2];
    const float* b1  = (const float*)d_in[3];
    const float* W2  = (const float*)d_in[4];
    const float* A2a = (const float*)d_in[5];
    const float* A2b = (const float*)d_in[6];
    const float* W3  = (const float*)d_in[7];
    const float* A3a = (const float*)d_in[8];
    const float* A3b = (const float*)d_in[9];
    const float* W4  = (const float*)d_in[10];
    const float* A4a = (const float*)d_in[11];
    const float* A4b = (const float*)d_in[12];
    float* out = (float*)d_out;

    float *px1, *px2;
    unsigned *ppH, *ppL;
    int *pcnt, *pfill;
    cudaGetSymbolAddress((void**)&px1, g_x1);
    cudaGetSymbolAddress((void**)&px2, g_x2);
    cudaGetSymbolAddress((void**)&ppH, g_pH);
    cudaGetSymbolAddress((void**)&ppL, g_pL);
    cudaGetSymbolAddress((void**)&pcnt, g_cnt);
    cudaGetSymbolAddress((void**)&pfill, g_fill);

    cudaFuncSetAttribute(k_block, cudaFuncAttributeMaxDynamicSharedMemorySize, BLK_SMEM);

    const int NB_GEMM = (N_NODES + 127) / 128;           // 391
    const int NB_E = (N_EDGES + 255) / 256;              // 3125
    const int NB_CSR = (N_NODES * 16 + 255) / 256;       // 3125

    // one-time host objects (no device work, no device allocation)
    static cudaStream_t sB = 0;
    static cudaEvent_t evFork = 0, evJoin = 0;
    static int sOK = -1;
    if (sOK < 0) {
        sOK = (cudaStreamCreateWithFlags(&sB, cudaStreamNonBlocking) == cudaSuccess &&
               cudaEventCreateWithFlags(&evFork, cudaEventDisableTiming) == cudaSuccess &&
               cudaEventCreateWithFlags(&evJoin, cudaEventDisableTiming) == cudaSuccess)
                  ? 1 : 0;
    }

    if (sOK) {
        // fork: CSR-build chain on sB, pack+layer1 on origin stream
        cudaEventRecord(evFork, 0);
        cudaStreamWaitEvent(sB, evFork, 0);

        k_zero_int<<<(N_NODES + 255) / 256, 256, 0, sB>>>(pcnt, pfill, N_NODES);
        k_deg<<<NB_E, 256, 0, sB>>>(edg);
        k_scan1<<<SCAN_B, 256, 0, sB>>>();
        k_scan2<<<1, 256, 0, sB>>>();
        k_scan3<<<SCAN_B, 256, 0, sB>>>();
        k_fill<<<NB_E, 256, 0, sB>>>(edg);
        cudaEventRecord(evJoin, sB);

        k_pack<<<(PACK_TOT + 255) / 256, 256>>>(W1, W2, A2a, A2b, W3, A3a, A3b, W4, A4a, A4b);
        k_layer1<<<NB_GEMM, 256>>>(x0, b1, px1);

        cudaStreamWaitEvent(0, evJoin, 0);   // join before first csr
    } else {
        k_zero_int<<<(N_NODES + 255) / 256, 256>>>(pcnt, pfill, N_NODES);
        k_deg<<<NB_E, 256>>>(edg);
        k_pack<<<(PACK_TOT + 255) / 256, 256>>>(W1, W2, A2a, A2b, W3, A3a, A3b, W4, A4a, A4b);
        k_layer1<<<NB_GEMM, 256>>>(x0, b1, px1);
        k_scan1<<<SCAN_B, 256>>>();
        k_scan2<<<1, 256>>>();
        k_scan3<<<SCAN_B, 256>>>();
        k_fill<<<NB_E, 256>>>(edg);
    }

    // block 2: x1 -> x2
    k_csr<<<NB_CSR, 256>>>(px1);
    k_block<<<NB_GEMM, 256, BLK_SMEM>>>(px1, ppH + PACK_B2, ppL + PACK_B2, px2);

    // block 3: x2 -> x1
    k_csr<<<NB_CSR, 256>>>(px2);
    k_block<<<NB_GEMM, 256, BLK_SMEM>>>(px2, ppH + PACK_B3, ppL + PACK_B3, px1);

    // block 4: x1 -> out
    k_csr<<<NB_CSR, 256>>>(px1);
    k_block<<<NB_GEMM, 256, BLK_SMEM>>>(px1, ppH + PACK_B4, ppL + PACK_B4, out);
}

// round 16
// speedup vs baseline: 1.1556x; 1.1556x over previous
#include <cuda_runtime.h>

#define N_NODES 50000
#define N_EDGES 800000
#define FEATS 128
#define HID 64

// ---------------- scratch (device globals; no allocation allowed) ----------
__device__ float g_x1[N_NODES * HID];
__device__ float g_x2[N_NODES * HID];
__device__ float g_h[N_NODES * HID];
__device__ float g_inv[N_NODES];
__device__ int   g_cnt[N_NODES];
__device__ int   g_fill[N_NODES];
__device__ int   g_rowptr[N_NODES + 1];
__device__ int   g_bsum[256];
__device__ int   g_boff[256];
__device__ int   g_esrc[N_EDGES];
__device__ float g_ecoef[N_EDGES];

// packed bf16x2 B-fragment tables (m16n8k16 layout)
// L1: 8 slots | per block-set: 16 slots (W 0-7, Aa 8-11, Ab 12-15)
// slot = 512 u32 (8 ntiles x 32 lanes x 2 regs)
#define PACK_L1 0
#define PACK_B2 4096
#define PACK_B3 (4096 + 8192)
#define PACK_B4 (4096 + 2 * 8192)
#define PACK_TOT (4096 + 3 * 8192)
__device__ unsigned g_pH[PACK_TOT];
__device__ unsigned g_pL[PACK_TOT];

__device__ __forceinline__ unsigned bfpack(float hv, float lv) {
    unsigned r;
    asm("cvt.rn.bf16x2.f32 %0, %1, %2;" : "=r"(r) : "f"(hv), "f"(lv));
    return r;
}
__device__ __forceinline__ float bflo(unsigned p) { return __uint_as_float(p << 16); }
__device__ __forceinline__ float bfhi(unsigned p) { return __uint_as_float(p & 0xffff0000u); }

__device__ __forceinline__ void bfsplit(float lv, float hv, unsigned& ph, unsigned& pl) {
    ph = bfpack(hv, lv);
    pl = bfpack(hv - bfhi(ph), lv - bflo(ph));
}

__device__ __forceinline__ void mma16(float* d, unsigned a0, unsigned a1,
                                      unsigned a2, unsigned a3,
                                      unsigned b0, unsigned b1) {
    asm volatile(
        "mma.sync.aligned.m16n8k16.row.col.f32.bf16.bf16.f32 "
        "{%0,%1,%2,%3}, {%4,%5,%6,%7}, {%8,%9}, {%0,%1,%2,%3};"
        : "+f"(d[0]), "+f"(d[1]), "+f"(d[2]), "+f"(d[3])
        : "r"(a0), "r"(a1), "r"(a2), "r"(a3), "r"(b0), "r"(b1));
}

__device__ __forceinline__ void mma3(float* d,
                                     unsigned ah0, unsigned ah1, unsigned ah2, unsigned ah3,
                                     unsigned al0, unsigned al1, unsigned al2, unsigned al3,
                                     unsigned bh0, unsigned bh1, unsigned bl0, unsigned bl1) {
    mma16(d, al0, al1, al2, al3, bh0, bh1);
    mma16(d, ah0, ah1, ah2, ah3, bl0, bl1);
    mma16(d, ah0, ah1, ah2, ah3, bh0, bh1);
}

// ---------------- graph prep ------------------------------------------------
__global__ void k_zero_int(int* a, int* b, int n) {
    int i = blockIdx.x * blockDim.x + threadIdx.x;
    if (i < n) { a[i] = 0; b[i] = 0; }
}

__global__ void k_deg(const int* __restrict__ edges) {
    int e = blockIdx.x * blockDim.x + threadIdx.x;
    if (e < N_EDGES) atomicAdd(&g_cnt[edges[N_EDGES + e]], 1);
}

#define SCAN_B ((N_NODES + 255) / 256)   // 196

__global__ void k_scan1() {
    __shared__ int sm[256];
    int b = blockIdx.x, t = threadIdx.x;
    int i = b * 256 + t;
    int v = (i < N_NODES) ? g_cnt[i] : 0;
    if (i < N_NODES) g_inv[i] = rsqrtf(fmaxf((float)v, 1.0f));
    sm[t] = v;
    __syncthreads();
    for (int off = 1; off < 256; off <<= 1) {
        int u = (t >= off) ? sm[t - off] : 0;
        __syncthreads();
        sm[t] += u;
        __syncthreads();
    }
    if (i < N_NODES) g_rowptr[i] = sm[t] - v;
    if (t == 255) g_bsum[b] = sm[255];
}

__global__ void k_scan2() {
    __shared__ int sm[256];
    int t = threadIdx.x;
    int v = (t < SCAN_B) ? g_bsum[t] : 0;
    sm[t] = v;
    __syncthreads();
    for (int off = 1; off < 256; off <<= 1) {
        int u = (t >= off) ? sm[t - off] : 0;
        __syncthreads();
        sm[t] += u;
        __syncthreads();
    }
    if (t < SCAN_B) g_boff[t] = sm[t] - v;
    if (t == 255) g_rowptr[N_NODES] = sm[255];
}

__global__ void k_scan3() {
    int i = blockIdx.x * 256 + threadIdx.x;
    if (i < N_NODES) g_rowptr[i] += g_boff[blockIdx.x];
}

__global__ void k_fill(const int* __restrict__ edges) {
    int e = blockIdx.x * blockDim.x + threadIdx.x;
    if (e < N_EDGES) {
        int s = edges[e];
        int d = edges[N_EDGES + e];
        int pos = g_rowptr[d] + atomicAdd(&g_fill[d], 1);
        g_esrc[pos] = s;
        g_ecoef[pos] = g_inv[s] * g_inv[d];
    }
}

// pack all layer weights into m16n8k16 B-fragment order, bf16 hi/lo split
__global__ void k_pack(
    const float* __restrict__ W1,
    const float* __restrict__ W2, const float* __restrict__ A2a, const float* __restrict__ A2b,
    const float* __restrict__ W3, const float* __restrict__ A3a, const float* __restrict__ A3b,
    const float* __restrict__ W4, const float* __restrict__ A4a, const float* __restrict__ A4b)
{
    int t = blockIdx.x * blockDim.x + threadIdx.x;
    if (t >= PACK_TOT) return;

    int s, rem;
    const float *W = 0, *Aa = 0, *Ab = 0;
    bool isL1 = (t < PACK_B2);
    if (isL1) {
        s = t >> 9; rem = t & 511; W = W1;
    } else {
        int r = (t - PACK_B2) >> 13;
        int within = (t - PACK_B2) & 8191;
        s = within >> 9; rem = within & 511;
        if (r == 0)      { W = W2; Aa = A2a; Ab = A2b; }
        else if (r == 1) { W = W3; Aa = A3a; Ab = A3b; }
        else             { W = W4; Aa = A4a; Ab = A4b; }
    }
    int nt = rem >> 6;
    int lane = (rem >> 1) & 31;
    int j = rem & 1;
    int tig = lane & 3, gid = lane >> 2;
    int n = nt * 8 + gid;
    int kk = 2 * tig + j * 8;

    float v0, v1;
    if (isL1 || s < 8) {
        int k = s * 16 + kk;
        v0 = W[n * 128 + k]; v1 = W[n * 128 + k + 1];
    } else if (s < 12) {
        int k = (s - 8) * 16 + kk;
        v0 = Aa[n * 64 + k]; v1 = Aa[n * 64 + k + 1];
    } else {
        int k = (s - 12) * 16 + kk;
        v0 = Ab[n * 64 + k]; v1 = Ab[n * 64 + k + 1];
    }
    unsigned ph, pl;
    bfsplit(v0, v1, ph, pl);
    g_pH[t] = ph;
    g_pL[t] = pl;
}

// ---------------- CSR pull aggregation: h[n] = sum_e coef*x[src] -----------
// 16 threads per node, thread q handles feats [4q, 4q+4)
__global__ __launch_bounds__(256) void k_csr(const float* __restrict__ x) {
    int idx = blockIdx.x * blockDim.x + threadIdx.x;
    int n = idx >> 4;
    if (n >= N_NODES) return;
    int q4 = (idx & 15) * 4;
    int beg = g_rowptr[n];
    int end = g_rowptr[n + 1];
    float4 acc = make_float4(0.f, 0.f, 0.f, 0.f);
    int e = beg;
    for (; e + 4 <= end; e += 4) {
        int s0 = g_esrc[e],     s1 = g_esrc[e + 1];
        int s2 = g_esrc[e + 2], s3 = g_esrc[e + 3];
        float c0 = g_ecoef[e],     c1 = g_ecoef[e + 1];
        float c2 = g_ecoef[e + 2], c3 = g_ecoef[e + 3];
        float4 v0 = *(const float4*)&x[s0 * HID + q4];
        float4 v1 = *(const float4*)&x[s1 * HID + q4];
        float4 v2 = *(const float4*)&x[s2 * HID + q4];
        float4 v3 = *(const float4*)&x[s3 * HID + q4];
        acc.x += v0.x * c0 + v1.x * c1 + v2.x * c2 + v3.x * c3;
        acc.y += v0.y * c0 + v1.y * c1 + v2.y * c2 + v3.y * c3;
        acc.z += v0.z * c0 + v1.z * c1 + v2.z * c2 + v3.z * c3;
        acc.w += v0.w * c0 + v1.w * c1 + v2.w * c2 + v3.w * c3;
    }
    for (; e < end; e++) {
        int s = g_esrc[e];
        float c = g_ecoef[e];
        float4 v = *(const float4*)&x[s * HID + q4];
        acc.x += v.x * c;
        acc.y += v.y * c;
        acc.z += v.z * c;
        acc.w += v.w * c;
    }
    *(float4*)&g_h[n * HID + q4] = acc;
}

// ---------------- layer 1: relu(x0 @ W1^T + b1), smem-free bf16x3 ----------
__global__ __launch_bounds__(256) void k_layer1(
    const float* __restrict__ x0, const float* __restrict__ b1,
    float* __restrict__ out)
{
    int tid = threadIdx.x;
    int lane = tid & 31, wid = tid >> 5;
    int tig = lane & 3, gid = lane >> 2;
    int nodeA = blockIdx.x * 128 + wid * 16 + gid;
    int nodeB = nodeA + 8;
    bool vA = nodeA < N_NODES, vB = nodeB < N_NODES;
    const float* xA = x0 + (long long)nodeA * FEATS;
    const float* xB = x0 + (long long)nodeB * FEATS;

    const unsigned* gH = g_pH + PACK_L1 + lane * 2;
    const unsigned* gL = g_pL + PACK_L1 + lane * 2;

    float acc[8][4] = {};
    const float2 z2 = make_float2(0.f, 0.f);

#pragma unroll 2
    for (int ks = 0; ks < 8; ks++) {
        int c = ks * 16 + 2 * tig;
        float2 fA0 = vA ? *(const float2*)&xA[c] : z2;
        float2 fA2 = vA ? *(const float2*)&xA[c + 8] : z2;
        float2 fB0 = vB ? *(const float2*)&xB[c] : z2;
        float2 fB2 = vB ? *(const float2*)&xB[c + 8] : z2;
        unsigned ah0, al0, ah1, al1, ah2, al2, ah3, al3;
        bfsplit(fA0.x, fA0.y, ah0, al0);
        bfsplit(fB0.x, fB0.y, ah1, al1);
        bfsplit(fA2.x, fA2.y, ah2, al2);
        bfsplit(fB2.x, fB2.y, ah3, al3);
        const unsigned* pH_ = gH + ks * 512;
        const unsigned* pL_ = gL + ks * 512;
#pragma unroll
        for (int nt = 0; nt < 8; nt++) {
            uint2 wh = *(const uint2*)(pH_ + nt * 64);
            uint2 wl = *(const uint2*)(pL_ + nt * 64);
            mma3(acc[nt], ah0, ah1, ah2, ah3, al0, al1, al2, al3, wh.x, wh.y, wl.x, wl.y);
        }
    }

#pragma unroll
    for (int nt = 0; nt < 8; nt++) {
        int col = nt * 8 + 2 * tig;
        float2 bb = *(const float2*)&b1[col];
        if (vA) {
            float2 o;
            o.x = fmaxf(acc[nt][0] + bb.x, 0.f);
            o.y = fmaxf(acc[nt][1] + bb.y, 0.f);
            *(float2*)&out[nodeA * HID + col] = o;
        }
        if (vB) {
            float2 o;
            o.x = fmaxf(acc[nt][2] + bb.x, 0.f);
            o.y = fmaxf(acc[nt][3] + bb.y, 0.f);
            *(float2*)&out[nodeB * HID + col] = o;
        }
    }
}

// ---------------- block: relu(cat[x,h]@W^T + (x@Aa^T)*(x@Ab^T)) ------------
// x/h staged in smem (coalesced, reused); B fragments (bf16) from L1.
#define XS_STRIDE 68
#define BLK_SMEM (128 * XS_STRIDE * 2 * 4)   // 69632 bytes

__global__ __launch_bounds__(256) void k_block(
    const float* __restrict__ x, const unsigned* __restrict__ pH,
    const unsigned* __restrict__ pL, float* __restrict__ out)
{
    extern __shared__ float sm[];
    float* xs = sm;                    // [128][68]
    float* hs = sm + 128 * XS_STRIDE;  // [128][68]

    int tid = threadIdx.x;
    int n0 = blockIdx.x * 128;

    for (int idx = tid; idx < 128 * 16; idx += 256) {
        int r = idx >> 4;
        int c4 = (idx & 15) * 4;
        int node = n0 + r;
        float4 xv, hv;
        if (node < N_NODES) {
            xv = *(const float4*)&x[node * HID + c4];
            hv = *(const float4*)&g_h[node * HID + c4];
        } else {
            xv = make_float4(0.f, 0.f, 0.f, 0.f);
            hv = xv;
        }
        *(float4*)&xs[r * XS_STRIDE + c4] = xv;
        *(float4*)&hs[r * XS_STRIDE + c4] = hv;
    }
    __syncthreads();

    int lane = tid & 31, wid = tid >> 5;
    int tig = lane & 3, gid = lane >> 2;
    int row0 = wid * 16 + gid;
    int nodeA = n0 + row0;
    int nodeB = nodeA + 8;
    bool vA = nodeA < N_NODES, vB = nodeB < N_NODES;

    const unsigned* gH = pH + lane * 2;
    const unsigned* gL = pL + lane * 2;

#pragma unroll 1
    for (int half = 0; half < 2; half++) {
        int ntoff = half * 4 * 64;
        float accW[4][4] = {}, accA[4][4] = {}, accB[4][4] = {};

        // phase X: A = x; W slots 0-3, Aa slots 8-11, Ab slots 12-15
#pragma unroll
        for (int ks = 0; ks < 4; ks++) {
            const float* xr = &xs[row0 * XS_STRIDE + ks * 16 + 2 * tig];
            float2 f0 = *(const float2*)xr;
            float2 f2 = *(const float2*)(xr + 8);
            float2 f1 = *(const float2*)(xr + 8 * XS_STRIDE);
            float2 f3 = *(const float2*)(xr + 8 * XS_STRIDE + 8);
            unsigned ah0, al0, ah1, al1, ah2, al2, ah3, al3;
            bfsplit(f0.x, f0.y, ah0, al0);
            bfsplit(f1.x, f1.y, ah1, al1);
            bfsplit(f2.x, f2.y, ah2, al2);
            bfsplit(f3.x, f3.y, ah3, al3);
#pragma unroll
            for (int nt = 0; nt < 4; nt++) {
                uint2 wh = *(const uint2*)(gH + ks * 512 + ntoff + nt * 64);
                uint2 wl = *(const uint2*)(gL + ks * 512 + ntoff + nt * 64);
                mma3(accW[nt], ah0, ah1, ah2, ah3, al0, al1, al2, al3, wh.x, wh.y, wl.x, wl.y);
                uint2 gh = *(const uint2*)(gH + (8 + ks) * 512 + ntoff + nt * 64);
                uint2 gl = *(const uint2*)(gL + (8 + ks) * 512 + ntoff + nt * 64);
                mma3(accA[nt], ah0, ah1, ah2, ah3, al0, al1, al2, al3, gh.x, gh.y, gl.x, gl.y);
                uint2 kh = *(const uint2*)(gH + (12 + ks) * 512 + ntoff + nt * 64);
                uint2 kl = *(const uint2*)(gL + (12 + ks) * 512 + ntoff + nt * 64);
                mma3(accB[nt], ah0, ah1, ah2, ah3, al0, al1, al2, al3, kh.x, kh.y, kl.x, kl.y);
            }
        }

        // phase H: A = h; W slots 4-7
#pragma unroll
        for (int ks = 0; ks < 4; ks++) {
            const float* hr = &hs[row0 * XS_STRIDE + ks * 16 + 2 * tig];
            float2 f0 = *(const float2*)hr;
            float2 f2 = *(const float2*)(hr + 8);
            float2 f1 = *(const float2*)(hr + 8 * XS_STRIDE);
            float2 f3 = *(const float2*)(hr + 8 * XS_STRIDE + 8);
            unsigned ah0, al0, ah1, al1, ah2, al2, ah3, al3;
            bfsplit(f0.x, f0.y, ah0, al0);
            bfsplit(f1.x, f1.y, ah1, al1);
            bfsplit(f2.x, f2.y, ah2, al2);
            bfsplit(f3.x, f3.y, ah3, al3);
#pragma unroll
            for (int nt = 0; nt < 4; nt++) {
                uint2 wh = *(const uint2*)(gH + (4 + ks) * 512 + ntoff + nt * 64);
                uint2 wl = *(const uint2*)(gL + (4 + ks) * 512 + ntoff + nt * 64);
                mma3(accW[nt], ah0, ah1, ah2, ah3, al0, al1, al2, al3, wh.x, wh.y, wl.x, wl.y);
            }
        }

#pragma unroll
        for (int nt = 0; nt < 4; nt++) {
            int col = half * 32 + nt * 8 + 2 * tig;
            if (vA) {
                float2 o;
                o.x = fmaxf(accW[nt][0] + accA[nt][0] * accB[nt][0], 0.f);
                o.y = fmaxf(accW[nt][1] + accA[nt][1] * accB[nt][1], 0.f);
                *(float2*)&out[nodeA * HID + col] = o;
            }
            if (vB) {
                float2 o;
                o.x = fmaxf(accW[nt][2] + accA[nt][2] * accB[nt][2], 0.f);
                o.y = fmaxf(accW[nt][3] + accA[nt][3] * accB[nt][3], 0.f);
                *(float2*)&out[nodeB * HID + col] = o;
            }
        }
    }
}

// ---------------- launch ----------------------------------------------------
extern "C" void kernel_launch(void* const* d_in, const int* in_sizes, int n_in,
                              void* d_out, int out_size)
{
    const float* x0 = (const float*)d_in[0];
    const int* edg  = (const int*)d_in[1];   // int32: [2][N_EDGES]
    const float* W1  = (const float*)d_in[2];
    const float* b1  = (const float*)d_in[3];
    const float* W2  = (const float*)d_in[4];
    const float* A2a = (const float*)d_in[5];
    const float* A2b = (const float*)d_in[6];
    const float* W3  = (const float*)d_in[7];
    const float* A3a = (const float*)d_in[8];
    const float* A3b = (const float*)d_in[9];
    const float* W4  = (const float*)d_in[10];
    const float* A4a = (const float*)d_in[11];
    const float* A4b = (const float*)d_in[12];
    float* out = (float*)d_out;

    float *px1, *px2;
    unsigned *ppH, *ppL;
    int *pcnt, *pfill;
    cudaGetSymbolAddress((void**)&px1, g_x1);
    cudaGetSymbolAddress((void**)&px2, g_x2);
    cudaGetSymbolAddress((void**)&ppH, g_pH);
    cudaGetSymbolAddress((void**)&ppL, g_pL);
    cudaGetSymbolAddress((void**)&pcnt, g_cnt);
    cudaGetSymbolAddress((void**)&pfill, g_fill);

    cudaFuncSetAttribute(k_block, cudaFuncAttributeMaxDynamicSharedMemorySize, BLK_SMEM);

    const int NB_GEMM = (N_NODES + 127) / 128;           // 391
    const int NB_E = (N_EDGES + 255) / 256;              // 3125
    const int NB_CSR = (N_NODES * 16 + 255) / 256;       // 3125

    // one-time host objects (no device work, no device allocation)
    static cudaStream_t sB = 0;
    static cudaEvent_t evFork = 0, evJoin = 0;
    static int sOK = -1;
    if (sOK < 0) {
        sOK = (cudaStreamCreateWithFlags(&sB, cudaStreamNonBlocking) == cudaSuccess &&
               cudaEventCreateWithFlags(&evFork, cudaEventDisableTiming) == cudaSuccess &&
               cudaEventCreateWithFlags(&evJoin, cudaEventDisableTiming) == cudaSuccess)
                  ? 1 : 0;
    }

    if (sOK) {
        // fork: CSR-build chain on sB, pack+layer1 on origin stream
        cudaEventRecord(evFork, 0);
        cudaStreamWaitEvent(sB, evFork, 0);

        k_zero_int<<<(N_NODES + 255) / 256, 256, 0, sB>>>(pcnt, pfill, N_NODES);
        k_deg<<<NB_E, 256, 0, sB>>>(edg);
        k_scan1<<<SCAN_B, 256, 0, sB>>>();
        k_scan2<<<1, 256, 0, sB>>>();
        k_scan3<<<SCAN_B, 256, 0, sB>>>();
        k_fill<<<NB_E, 256, 0, sB>>>(edg);
        cudaEventRecord(evJoin, sB);

        k_pack<<<(PACK_TOT + 255) / 256, 256>>>(W1, W2, A2a, A2b, W3, A3a, A3b, W4, A4a, A4b);
        k_layer1<<<NB_GEMM, 256>>>(x0, b1, px1);

        cudaStreamWaitEvent(0, evJoin, 0);   // join before first csr
    } else {
        k_zero_int<<<(N_NODES + 255) / 256, 256>>>(pcnt, pfill, N_NODES);
        k_deg<<<NB_E, 256>>>(edg);
        k_pack<<<(PACK_TOT + 255) / 256, 256>>>(W1, W2, A2a, A2b, W3, A3a, A3b, W4, A4a, A4b);
        k_layer1<<<NB_GEMM, 256>>>(x0, b1, px1);
        k_scan1<<<SCAN_B, 256>>>();
        k_scan2<<<1, 256>>>();
        k_scan3<<<SCAN_B, 256>>>();
        k_fill<<<NB_E, 256>>>(edg);
    }

    // block 2: x1 -> x2
    k_csr<<<NB_CSR, 256>>>(px1);
    k_block<<<NB_GEMM, 256, BLK_SMEM>>>(px1, ppH + PACK_B2, ppL + PACK_B2, px2);

    // block 3: x2 -> x1
    k_csr<<<NB_CSR, 256>>>(px2);
    k_block<<<NB_GEMM, 256, BLK_SMEM>>>(px2, ppH + PACK_B3, ppL + PACK_B3, px1);

    // block 4: x1 -> out
    k_csr<<<NB_CSR, 256>>>(px1);
    k_block<<<NB_GEMM, 256, BLK_SMEM>>>(px1, ppH + PACK_B4, ppL + PACK_B4, out);
}

// round 17
// speedup vs baseline: 1.3077x; 1.1317x over previous
#include <cuda_runtime.h>

#define N_NODES 50000
#define N_EDGES 800000
#define FEATS 128
#define HID 64

// ---------------- scratch (device globals; no allocation allowed) ----------
__device__ float g_x1[N_NODES * HID];
__device__ float g_x2[N_NODES * HID];
__device__ float g_h[N_NODES * HID];
__device__ float g_inv[N_NODES];
__device__ int   g_cnt[N_NODES];
__device__ int   g_fill[N_NODES];
__device__ int   g_rowptr[N_NODES + 1];
__device__ int   g_bsum[256];
__device__ int   g_boff[256];
__device__ int   g_esrc[N_EDGES];
__device__ float g_ecoef[N_EDGES];

// packed bf16x2 B-fragment tables (m16n8k16 layout)
// L1: 8 slots | per block-set: 16 slots (W 0-7, Aa 8-11, Ab 12-15)
// slot = 512 u32 (8 ntiles x 32 lanes x 2 regs)
#define PACK_L1 0
#define PACK_B2 4096
#define PACK_B3 (4096 + 8192)
#define PACK_B4 (4096 + 2 * 8192)
#define PACK_TOT (4096 + 3 * 8192)
__device__ unsigned g_pH[PACK_TOT];
__device__ unsigned g_pL[PACK_TOT];

__device__ __forceinline__ unsigned bfpack(float hv, float lv) {
    unsigned r;
    asm("cvt.rn.bf16x2.f32 %0, %1, %2;" : "=r"(r) : "f"(hv), "f"(lv));
    return r;
}
__device__ __forceinline__ float bflo(unsigned p) { return __uint_as_float(p << 16); }
__device__ __forceinline__ float bfhi(unsigned p) { return __uint_as_float(p & 0xffff0000u); }

__device__ __forceinline__ void bfsplit(float lv, float hv, unsigned& ph, unsigned& pl) {
    ph = bfpack(hv, lv);
    pl = bfpack(hv - bfhi(ph), lv - bflo(ph));
}

__device__ __forceinline__ void mma16(float* d, unsigned a0, unsigned a1,
                                      unsigned a2, unsigned a3,
                                      unsigned b0, unsigned b1) {
    asm volatile(
        "mma.sync.aligned.m16n8k16.row.col.f32.bf16.bf16.f32 "
        "{%0,%1,%2,%3}, {%4,%5,%6,%7}, {%8,%9}, {%0,%1,%2,%3};"
        : "+f"(d[0]), "+f"(d[1]), "+f"(d[2]), "+f"(d[3])
        : "r"(a0), "r"(a1), "r"(a2), "r"(a3), "r"(b0), "r"(b1));
}

__device__ __forceinline__ void mma3(float* d,
                                     unsigned ah0, unsigned ah1, unsigned ah2, unsigned ah3,
                                     unsigned al0, unsigned al1, unsigned al2, unsigned al3,
                                     unsigned bh0, unsigned bh1, unsigned bl0, unsigned bl1) {
    mma16(d, al0, al1, al2, al3, bh0, bh1);
    mma16(d, ah0, ah1, ah2, ah3, bl0, bl1);
    mma16(d, ah0, ah1, ah2, ah3, bh0, bh1);
}

// ---------------- graph prep ------------------------------------------------
__global__ void k_zero_int(int* a, int* b, int n) {
    int i = blockIdx.x * blockDim.x + threadIdx.x;
    if (i < n) { a[i] = 0; b[i] = 0; }
}

__global__ void k_deg(const int* __restrict__ edges) {
    int e = blockIdx.x * blockDim.x + threadIdx.x;
    if (e < N_EDGES) atomicAdd(&g_cnt[edges[N_EDGES + e]], 1);
}

#define SCAN_B ((N_NODES + 255) / 256)   // 196

__global__ void k_scan1() {
    __shared__ int sm[256];
    int b = blockIdx.x, t = threadIdx.x;
    int i = b * 256 + t;
    int v = (i < N_NODES) ? g_cnt[i] : 0;
    if (i < N_NODES) g_inv[i] = rsqrtf(fmaxf((float)v, 1.0f));
    sm[t] = v;
    __syncthreads();
    for (int off = 1; off < 256; off <<= 1) {
        int u = (t >= off) ? sm[t - off] : 0;
        __syncthreads();
        sm[t] += u;
        __syncthreads();
    }
    if (i < N_NODES) g_rowptr[i] = sm[t] - v;
    if (t == 255) g_bsum[b] = sm[255];
}

__global__ void k_scan2() {
    __shared__ int sm[256];
    int t = threadIdx.x;
    int v = (t < SCAN_B) ? g_bsum[t] : 0;
    sm[t] = v;
    __syncthreads();
    for (int off = 1; off < 256; off <<= 1) {
        int u = (t >= off) ? sm[t - off] : 0;
        __syncthreads();
        sm[t] += u;
        __syncthreads();
    }
    if (t < SCAN_B) g_boff[t] = sm[t] - v;
    if (t == 255) g_rowptr[N_NODES] = sm[255];
}

__global__ void k_scan3() {
    int i = blockIdx.x * 256 + threadIdx.x;
    if (i < N_NODES) g_rowptr[i] += g_boff[blockIdx.x];
}

__global__ void k_fill(const int* __restrict__ edges) {
    int e = blockIdx.x * blockDim.x + threadIdx.x;
    if (e < N_EDGES) {
        int s = edges[e];
        int d = edges[N_EDGES + e];
        int pos = g_rowptr[d] + atomicAdd(&g_fill[d], 1);
        g_esrc[pos] = s;
        g_ecoef[pos] = g_inv[s] * g_inv[d];
    }
}

// pack all layer weights into m16n8k16 B-fragment order, bf16 hi/lo split
__global__ void k_pack(
    const float* __restrict__ W1,
    const float* __restrict__ W2, const float* __restrict__ A2a, const float* __restrict__ A2b,
    const float* __restrict__ W3, const float* __restrict__ A3a, const float* __restrict__ A3b,
    const float* __restrict__ W4, const float* __restrict__ A4a, const float* __restrict__ A4b)
{
    int t = blockIdx.x * blockDim.x + threadIdx.x;
    if (t >= PACK_TOT) return;

    int s, rem;
    const float *W = 0, *Aa = 0, *Ab = 0;
    bool isL1 = (t < PACK_B2);
    if (isL1) {
        s = t >> 9; rem = t & 511; W = W1;
    } else {
        int r = (t - PACK_B2) >> 13;
        int within = (t - PACK_B2) & 8191;
        s = within >> 9; rem = within & 511;
        if (r == 0)      { W = W2; Aa = A2a; Ab = A2b; }
        else if (r == 1) { W = W3; Aa = A3a; Ab = A3b; }
        else             { W = W4; Aa = A4a; Ab = A4b; }
    }
    int nt = rem >> 6;
    int lane = (rem >> 1) & 31;
    int j = rem & 1;
    int tig = lane & 3, gid = lane >> 2;
    int n = nt * 8 + gid;
    int kk = 2 * tig + j * 8;

    float v0, v1;
    if (isL1 || s < 8) {
        int k = s * 16 + kk;
        v0 = W[n * 128 + k]; v1 = W[n * 128 + k + 1];
    } else if (s < 12) {
        int k = (s - 8) * 16 + kk;
        v0 = Aa[n * 64 + k]; v1 = Aa[n * 64 + k + 1];
    } else {
        int k = (s - 12) * 16 + kk;
        v0 = Ab[n * 64 + k]; v1 = Ab[n * 64 + k + 1];
    }
    unsigned ph, pl;
    bfsplit(v0, v1, ph, pl);
    g_pH[t] = ph;
    g_pL[t] = pl;
}

// ---------------- CSR pull aggregation: h[n] = sum_e coef*x[src] -----------
// 16 threads per node, thread q handles feats [4q, 4q+4)
__global__ __launch_bounds__(256) void k_csr(const float* __restrict__ x) {
    int idx = blockIdx.x * blockDim.x + threadIdx.x;
    int n = idx >> 4;
    if (n >= N_NODES) return;
    int q4 = (idx & 15) * 4;
    int beg = g_rowptr[n];
    int end = g_rowptr[n + 1];
    float4 acc = make_float4(0.f, 0.f, 0.f, 0.f);
    int e = beg;
    for (; e + 4 <= end; e += 4) {
        int s0 = g_esrc[e],     s1 = g_esrc[e + 1];
        int s2 = g_esrc[e + 2], s3 = g_esrc[e + 3];
        float c0 = g_ecoef[e],     c1 = g_ecoef[e + 1];
        float c2 = g_ecoef[e + 2], c3 = g_ecoef[e + 3];
        float4 v0 = *(const float4*)&x[s0 * HID + q4];
        float4 v1 = *(const float4*)&x[s1 * HID + q4];
        float4 v2 = *(const float4*)&x[s2 * HID + q4];
        float4 v3 = *(const float4*)&x[s3 * HID + q4];
        acc.x += v0.x * c0 + v1.x * c1 + v2.x * c2 + v3.x * c3;
        acc.y += v0.y * c0 + v1.y * c1 + v2.y * c2 + v3.y * c3;
        acc.z += v0.z * c0 + v1.z * c1 + v2.z * c2 + v3.z * c3;
        acc.w += v0.w * c0 + v1.w * c1 + v2.w * c2 + v3.w * c3;
    }
    for (; e < end; e++) {
        int s = g_esrc[e];
        float c = g_ecoef[e];
        float4 v = *(const float4*)&x[s * HID + q4];
        acc.x += v.x * c;
        acc.y += v.y * c;
        acc.z += v.z * c;
        acc.w += v.w * c;
    }
    *(float4*)&g_h[n * HID + q4] = acc;
}

// ---------------- layer 1: relu(x0 @ W1^T + b1), smem-free bf16x3 ----------
__global__ __launch_bounds__(256) void k_layer1(
    const float* __restrict__ x0, const float* __restrict__ b1,
    float* __restrict__ out)
{
    int tid = threadIdx.x;
    int lane = tid & 31, wid = tid >> 5;
    int tig = lane & 3, gid = lane >> 2;
    int nodeA = blockIdx.x * 128 + wid * 16 + gid;
    int nodeB = nodeA + 8;
    bool vA = nodeA < N_NODES, vB = nodeB < N_NODES;
    const float* xA = x0 + (long long)nodeA * FEATS;
    const float* xB = x0 + (long long)nodeB * FEATS;

    const unsigned* gH = g_pH + PACK_L1 + lane * 2;
    const unsigned* gL = g_pL + PACK_L1 + lane * 2;

    float acc[8][4] = {};
    const float2 z2 = make_float2(0.f, 0.f);

#pragma unroll 2
    for (int ks = 0; ks < 8; ks++) {
        int c = ks * 16 + 2 * tig;
        float2 fA0 = vA ? *(const float2*)&xA[c] : z2;
        float2 fA2 = vA ? *(const float2*)&xA[c + 8] : z2;
        float2 fB0 = vB ? *(const float2*)&xB[c] : z2;
        float2 fB2 = vB ? *(const float2*)&xB[c + 8] : z2;
        unsigned ah0, al0, ah1, al1, ah2, al2, ah3, al3;
        bfsplit(fA0.x, fA0.y, ah0, al0);
        bfsplit(fB0.x, fB0.y, ah1, al1);
        bfsplit(fA2.x, fA2.y, ah2, al2);
        bfsplit(fB2.x, fB2.y, ah3, al3);
        const unsigned* pH_ = gH + ks * 512;
        const unsigned* pL_ = gL + ks * 512;
#pragma unroll
        for (int nt = 0; nt < 8; nt++) {
            uint2 wh = *(const uint2*)(pH_ + nt * 64);
            uint2 wl = *(const uint2*)(pL_ + nt * 64);
            mma3(acc[nt], ah0, ah1, ah2, ah3, al0, al1, al2, al3, wh.x, wh.y, wl.x, wl.y);
        }
    }

#pragma unroll
    for (int nt = 0; nt < 8; nt++) {
        int col = nt * 8 + 2 * tig;
        float2 bb = *(const float2*)&b1[col];
        if (vA) {
            float2 o;
            o.x = fmaxf(acc[nt][0] + bb.x, 0.f);
            o.y = fmaxf(acc[nt][1] + bb.y, 0.f);
            *(float2*)&out[nodeA * HID + col] = o;
        }
        if (vB) {
            float2 o;
            o.x = fmaxf(acc[nt][2] + bb.x, 0.f);
            o.y = fmaxf(acc[nt][3] + bb.y, 0.f);
            *(float2*)&out[nodeB * HID + col] = o;
        }
    }
}

// ---------------- block: relu(cat[x,h]@W^T + (x@Aa^T)*(x@Ab^T)) ------------
// x/h staged in smem (coalesced, reused); B fragments (bf16) from L1.
#define XS_STRIDE 68
#define BLK_SMEM (128 * XS_STRIDE * 2 * 4)   // 69632 bytes

__global__ __launch_bounds__(256) void k_block(
    const float* __restrict__ x, const unsigned* __restrict__ pH,
    const unsigned* __restrict__ pL, float* __restrict__ out)
{
    extern __shared__ float sm[];
    float* xs = sm;                    // [128][68]
    float* hs = sm + 128 * XS_STRIDE;  // [128][68]

    int tid = threadIdx.x;
    int n0 = blockIdx.x * 128;

    for (int idx = tid; idx < 128 * 16; idx += 256) {
        int r = idx >> 4;
        int c4 = (idx & 15) * 4;
        int node = n0 + r;
        float4 xv, hv;
        if (node < N_NODES) {
            xv = *(const float4*)&x[node * HID + c4];
            hv = *(const float4*)&g_h[node * HID + c4];
        } else {
            xv = make_float4(0.f, 0.f, 0.f, 0.f);
            hv = xv;
        }
        *(float4*)&xs[r * XS_STRIDE + c4] = xv;
        *(float4*)&hs[r * XS_STRIDE + c4] = hv;
    }
    __syncthreads();

    int lane = tid & 31, wid = tid >> 5;
    int tig = lane & 3, gid = lane >> 2;
    int row0 = wid * 16 + gid;
    int nodeA = n0 + row0;
    int nodeB = nodeA + 8;
    bool vA = nodeA < N_NODES, vB = nodeB < N_NODES;

    const unsigned* gH = pH + lane * 2;
    const unsigned* gL = pL + lane * 2;

#pragma unroll 1
    for (int half = 0; half < 2; half++) {
        int ntoff = half * 4 * 64;
        float accW[4][4] = {}, accA[4][4] = {}, accB[4][4] = {};

        // phase X: A = x; W slots 0-3, Aa slots 8-11, Ab slots 12-15
        for (int ks = 0; ks < 4; ks++) {
            const float* xr = &xs[row0 * XS_STRIDE + ks * 16 + 2 * tig];
            float2 f0 = *(const float2*)xr;
            float2 f2 = *(const float2*)(xr + 8);
            float2 f1 = *(const float2*)(xr + 8 * XS_STRIDE);
            float2 f3 = *(const float2*)(xr + 8 * XS_STRIDE + 8);
            unsigned ah0, al0, ah1, al1, ah2, al2, ah3, al3;
            bfsplit(f0.x, f0.y, ah0, al0);
            bfsplit(f1.x, f1.y, ah1, al1);
            bfsplit(f2.x, f2.y, ah2, al2);
            bfsplit(f3.x, f3.y, ah3, al3);
#pragma unroll
            for (int nt = 0; nt < 4; nt++) {
                uint2 wh = *(const uint2*)(gH + ks * 512 + ntoff + nt * 64);
                uint2 wl = *(const uint2*)(gL + ks * 512 + ntoff + nt * 64);
                mma3(accW[nt], ah0, ah1, ah2, ah3, al0, al1, al2, al3, wh.x, wh.y, wl.x, wl.y);
                uint2 gh = *(const uint2*)(gH + (8 + ks) * 512 + ntoff + nt * 64);
                uint2 gl = *(const uint2*)(gL + (8 + ks) * 512 + ntoff + nt * 64);
                mma3(accA[nt], ah0, ah1, ah2, ah3, al0, al1, al2, al3, gh.x, gh.y, gl.x, gl.y);
                uint2 kh = *(const uint2*)(gH + (12 + ks) * 512 + ntoff + nt * 64);
                uint2 kl = *(const uint2*)(gL + (12 + ks) * 512 + ntoff + nt * 64);
                mma3(accB[nt], ah0, ah1, ah2, ah3, al0, al1, al2, al3, kh.x, kh.y, kl.x, kl.y);
            }
        }

        // phase H: A = h; W slots 4-7
        for (int ks = 0; ks < 4; ks++) {
            const float* hr = &hs[row0 * XS_STRIDE + ks * 16 + 2 * tig];
            float2 f0 = *(const float2*)hr;
            float2 f2 = *(const float2*)(hr + 8);
            float2 f1 = *(const float2*)(hr + 8 * XS_STRIDE);
            float2 f3 = *(const float2*)(hr + 8 * XS_STRIDE + 8);
            unsigned ah0, al0, ah1, al1, ah2, al2, ah3, al3;
            bfsplit(f0.x, f0.y, ah0, al0);
            bfsplit(f1.x, f1.y, ah1, al1);
            bfsplit(f2.x, f2.y, ah2, al2);
            bfsplit(f3.x, f3.y, ah3, al3);
#pragma unroll
            for (int nt = 0; nt < 4; nt++) {
                uint2 wh = *(const uint2*)(gH + (4 + ks) * 512 + ntoff + nt * 64);
                uint2 wl = *(const uint2*)(gL + (4 + ks) * 512 + ntoff + nt * 64);
                mma3(accW[nt], ah0, ah1, ah2, ah3, al0, al1, al2, al3, wh.x, wh.y, wl.x, wl.y);
            }
        }

#pragma unroll
        for (int nt = 0; nt < 4; nt++) {
            int col = half * 32 + nt * 8 + 2 * tig;
            if (vA) {
                float2 o;
                o.x = fmaxf(accW[nt][0] + accA[nt][0] * accB[nt][0], 0.f);
                o.y = fmaxf(accW[nt][1] + accA[nt][1] * accB[nt][1], 0.f);
                *(float2*)&out[nodeA * HID + col] = o;
            }
            if (vB) {
                float2 o;
                o.x = fmaxf(accW[nt][2] + accA[nt][2] * accB[nt][2], 0.f);
                o.y = fmaxf(accW[nt][3] + accA[nt][3] * accB[nt][3], 0.f);
                *(float2*)&out[nodeB * HID + col] = o;
            }
        }
    }
}

// ---------------- launch ----------------------------------------------------
extern "C" void kernel_launch(void* const* d_in, const int* in_sizes, int n_in,
                              void* d_out, int out_size)
{
    const float* x0 = (const float*)d_in[0];
    const int* edg  = (const int*)d_in[1];   // int32: [2][N_EDGES]
    const float* W1  = (const float*)d_in[2];
    const float* b1  = (const float*)d_in[3];
    const float* W2  = (const float*)d_in[4];
    const float* A2a = (const float*)d_in[5];
    const float* A2b = (const float*)d_in[6];
    const float* W3  = (const float*)d_in[7];
    const float* A3a = (const float*)d_in[8];
    const float* A3b = (const float*)d_in[9];
    const float* W4  = (const float*)d_in[10];
    const float* A4a = (const float*)d_in[11];
    const float* A4b = (const float*)d_in[12];
    float* out = (float*)d_out;

    float *px1, *px2;
    unsigned *ppH, *ppL;
    int *pcnt, *pfill;
    cudaGetSymbolAddress((void**)&px1, g_x1);
    cudaGetSymbolAddress((void**)&px2, g_x2);
    cudaGetSymbolAddress((void**)&ppH, g_pH);
    cudaGetSymbolAddress((void**)&ppL, g_pL);
    cudaGetSymbolAddress((void**)&pcnt, g_cnt);
    cudaGetSymbolAddress((void**)&pfill, g_fill);

    cudaFuncSetAttribute(k_block, cudaFuncAttributeMaxDynamicSharedMemorySize, BLK_SMEM);

    const int NB_GEMM = (N_NODES + 127) / 128;           // 391
    const int NB_E = (N_EDGES + 255) / 256;              // 3125
    const int NB_CSR = (N_NODES * 16 + 255) / 256;       // 3125

    // one-time host objects (no device work, no device allocation)
    static cudaStream_t sB = 0;
    static cudaEvent_t evFork = 0, evJoin = 0;
    static int sOK = -1;
    if (sOK < 0) {
        sOK = (cudaStreamCreateWithFlags(&sB, cudaStreamNonBlocking) == cudaSuccess &&
               cudaEventCreateWithFlags(&evFork, cudaEventDisableTiming) == cudaSuccess &&
               cudaEventCreateWithFlags(&evJoin, cudaEventDisableTiming) == cudaSuccess)
                  ? 1 : 0;
    }

    if (sOK) {
        // fork: CSR-build chain on sB, pack+layer1 on origin stream
        cudaEventRecord(evFork, 0);
        cudaStreamWaitEvent(sB, evFork, 0);

        k_zero_int<<<(N_NODES + 255) / 256, 256, 0, sB>>>(pcnt, pfill, N_NODES);
        k_deg<<<NB_E, 256, 0, sB>>>(edg);
        k_scan1<<<SCAN_B, 256, 0, sB>>>();
        k_scan2<<<1, 256, 0, sB>>>();
        k_scan3<<<SCAN_B, 256, 0, sB>>>();
        k_fill<<<NB_E, 256, 0, sB>>>(edg);
        cudaEventRecord(evJoin, sB);

        k_pack<<<(PACK_TOT + 255) / 256, 256>>>(W1, W2, A2a, A2b, W3, A3a, A3b, W4, A4a, A4b);
        k_layer1<<<NB_GEMM, 256>>>(x0, b1, px1);

        cudaStreamWaitEvent(0, evJoin, 0);   // join before first csr
    } else {
        k_zero_int<<<(N_NODES + 255) / 256, 256>>>(pcnt, pfill, N_NODES);
        k_deg<<<NB_E, 256>>>(edg);
        k_pack<<<(PACK_TOT + 255) / 256, 256>>>(W1, W2, A2a, A2b, W3, A3a, A3b, W4, A4a, A4b);
        k_layer1<<<NB_GEMM, 256>>>(x0, b1, px1);
        k_scan1<<<SCAN_B, 256>>>();
        k_scan2<<<1, 256>>>();
        k_scan3<<<SCAN_B, 256>>>();
        k_fill<<<NB_E, 256>>>(edg);
    }

    // block 2: x1 -> x2
    k_csr<<<NB_CSR, 256>>>(px1);
    k_block<<<NB_GEMM, 256, BLK_SMEM>>>(px1, ppH + PACK_B2, ppL + PACK_B2, px2);

    // block 3: x2 -> x1
    k_csr<<<NB_CSR, 256>>>(px2);
    k_block<<<NB_GEMM, 256, BLK_SMEM>>>(px2, ppH + PACK_B3, ppL + PACK_B3, px1);

    // block 4: x1 -> out
    k_csr<<<NB_CSR, 256>>>(px1);
    k_block<<<NB_GEMM, 256, BLK_SMEM>>>(px1, ppH + PACK_B4, ppL + PACK_B4, out);
}